// round 8
// baseline (speedup 1.0000x reference)
#include <cuda_runtime.h>

// Fixed problem shapes
#define BD 2
#define FD 32
#define CD 5
#define DHW 884736           // 96^3
#define Q4 (DHW/4)           // 221184
#define NVOX (BD*DHW)        // 1769472
#define NG (NVOX/4)          // 442368
#define NFEAT (BD*FD*DHW)    // 56623104
#define PLO 15872            // conf in [0.2,1.0] -> 16-bit prefix within [PLO, PLO+512)
#define NBIN 512
#define NSLOT 20             // 5 classes x 4 order statistics
#define SPIKE_PRE 16256      // 0x3F80 : bin containing ONLY conf == 1.0f
#define HGRID 592

// ---------------- device scratch ----------------
__device__ __align__(16) unsigned g_packed[NVOX];   // label<<29 | (conf bits & 0x1FFFFFFF)
__device__ unsigned g_hist1[CD * NBIN];
__device__ unsigned g_hist2[NSLOT * 256];
__device__ unsigned g_hist3[NSLOT * 256];
__device__ int      g_t2_pre[NSLOT];
__device__ unsigned g_t2_rank[NSLOT];
__device__ unsigned g_n[CD];
__device__ double   g_g05[CD], g_g95[CD];
__device__ float    g_newmin[CD], g_newmax[CD];
__device__ unsigned g_done;

__device__ __forceinline__ unsigned unpack_bits(unsigned pk) {
    return (pk & 0x1FFFFFFFu) | 0x20000000u;
}

// ---------------- K0: zero ----------------
__global__ void k_zero() {
    int i = blockIdx.x * blockDim.x + threadIdx.x;
    int stride = gridDim.x * blockDim.x;
    for (int j = i; j < CD * NBIN; j += stride) g_hist1[j] = 0;
    for (int j = i; j < NSLOT * 256; j += stride) { g_hist2[j] = 0; g_hist3[j] = 0; }
    if (i == 0) g_done = 0;
}

// ---------------- K1: confidence + packed store + level-1 hist (warp-aggregated) ----
__device__ __forceinline__ float conf5(float a, float b, float c, float d, float e) {
    float y0 = a * 10.0f, y1 = b * 10.0f, y2 = c * 10.0f, y3 = d * 10.0f, y4 = e * 10.0f;
    float m = fmaxf(fmaxf(fmaxf(y0, y1), fmaxf(y2, y3)), y4);
    float s = expf(y0 - m) + expf(y1 - m) + expf(y2 - m) + expf(y3 - m) + expf(y4 - m);
    return 1.0f / s;
}

__global__ void k_conf(const float4* __restrict__ lg, const int4* __restrict__ lb) {
    __shared__ unsigned sh[CD * NBIN];
    for (int j = threadIdx.x; j < CD * NBIN; j += blockDim.x) sh[j] = 0;
    __syncthreads();
    int lane = threadIdx.x & 31;
    int stride = gridDim.x * blockDim.x;
    for (int g = blockIdx.x * blockDim.x + threadIdx.x; g < NG; g += stride) {
        int v = g * 4;
        int b = (v >= DHW) ? 1 : 0;
        int s4 = g - b * Q4;
        size_t base = (size_t)(b * CD) * Q4 + (size_t)s4;
        float4 L0 = __ldcs(&lg[base]);
        float4 L1 = __ldcs(&lg[base + Q4]);
        float4 L2 = __ldcs(&lg[base + 2 * (size_t)Q4]);
        float4 L3 = __ldcs(&lg[base + 3 * (size_t)Q4]);
        float4 L4 = __ldcs(&lg[base + 4 * (size_t)Q4]);
        float cf[4];
        cf[0] = conf5(L0.x, L1.x, L2.x, L3.x, L4.x);
        cf[1] = conf5(L0.y, L1.y, L2.y, L3.y, L4.y);
        cf[2] = conf5(L0.z, L1.z, L2.z, L3.z, L4.z);
        cf[3] = conf5(L0.w, L1.w, L2.w, L3.w, L4.w);
        int4 li = __ldcs(&lb[g]);
        int cc[4] = { li.x, li.y, li.z, li.w };
        unsigned pk[4];
#pragma unroll
        for (int k = 0; k < 4; k++) {
            unsigned bits = __float_as_uint(cf[k]);
            pk[k] = ((unsigned)cc[k] << 29) | (bits & 0x1FFFFFFFu);
            unsigned idx = (bits >> 16) - PLO;
            bool valid = idx < NBIN;
            unsigned key = valid ? ((unsigned)cc[k] * NBIN + idx) : (0x80000000u | (unsigned)lane);
            unsigned mset = __match_any_sync(0xffffffffu, key);
            if (valid && lane == (__ffs(mset) - 1))
                atomicAdd(&sh[key], (unsigned)__popc(mset));
        }
        __stcs((uint4*)g_packed + g, make_uint4(pk[0], pk[1], pk[2], pk[3]));
    }
    __syncthreads();
    for (int j = threadIdx.x; j < CD * NBIN; j += blockDim.x) {
        unsigned u = sh[j];
        if (u) atomicAdd(&g_hist1[j], u);
    }
}

// ---------------- K2: find2 prologue + level-2 histogram (compact targets) --------
__global__ void k_hist2() {
    __shared__ unsigned shh[NSLOT * 256];
    __shared__ int      spre[NSLOT];
    __shared__ unsigned srank[NSLOT];
    __shared__ int      ent_key[CD * 4];
    __shared__ int      ent_slot[CD * 4];
    __shared__ int      s_m;
    __shared__ unsigned swsum[8], swpre[8];
    __shared__ unsigned s_n;

    int t = threadIdx.x, lane = t & 31, warp = t >> 5;
    if (t < NSLOT) { spre[t] = -1; srank[t] = 0; }
    __syncthreads();

    // find2: scan 512-bin prefix histogram per class (2 bins/thread)
    for (int c = 0; c < CD; c++) {
        unsigned a = g_hist1[c * NBIN + 2 * t];
        unsigned b = g_hist1[c * NBIN + 2 * t + 1];
        unsigned s = a + b;
        unsigned incl = s;
        for (int off = 1; off < 32; off <<= 1) {
            unsigned u = __shfl_up_sync(0xffffffffu, incl, off);
            if (lane >= off) incl += u;
        }
        if (lane == 31) swsum[warp] = incl;
        __syncthreads();
        if (t == 0) {
            unsigned run = 0;
#pragma unroll
            for (int w = 0; w < 8; w++) { swpre[w] = run; run += swsum[w]; }
            s_n = run;
        }
        __syncthreads();
        unsigned total = s_n;
        long long exclp = (long long)(incl - s + swpre[warp]);
        long long n = (long long)total;
        if (n == 0) {
            if (t == 0 && blockIdx.x == 0) { g_n[c] = 0; g_g05[c] = 0.0; g_g95[c] = 0.0; }
        } else {
            double p05 = 0.05 * (double)(n - 1);
            long long i05 = (long long)p05;
            double p95 = 0.95 * (double)(n - 1);
            long long i95 = (long long)p95;
            if (t == 0 && blockIdx.x == 0) {
                g_n[c] = total;
                g_g05[c] = p05 - (double)i05;
                g_g95[c] = p95 - (double)i95;
            }
            long long rr[4];
            rr[0] = i05; rr[1] = (i05 + 1 < n) ? i05 + 1 : i05;
            rr[2] = i95; rr[3] = (i95 + 1 < n) ? i95 + 1 : i95;
#pragma unroll
            for (int j = 0; j < 4; j++) {
                long long r = rr[j];
                if (r >= exclp && r < exclp + (long long)s) {
                    unsigned rem = (unsigned)(r - exclp);
                    if (rem < a) { spre[c * 4 + j] = PLO + 2 * t;     srank[c * 4 + j] = rem; }
                    else         { spre[c * 4 + j] = PLO + 2 * t + 1; srank[c * 4 + j] = rem - a; }
                }
            }
        }
        __syncthreads();
    }
    // Build compact target list: dedup + spike-resolved slots dropped entirely
    if (t == 0) {
        int mmax = 0;
        for (int c = 0; c < CD; c++) {
            int m = 0;
            for (int j = 0; j < 4; j++) {
                int pre = spre[c * 4 + j];
                if (pre < 0 || pre == SPIKE_PRE) continue;
                bool dup = false;
                for (int j2 = 0; j2 < j; j2++) if (spre[c * 4 + j2] == pre) { dup = true; break; }
                if (!dup) { ent_key[c * 4 + m] = pre; ent_slot[c * 4 + m] = c * 4 + j; m++; }
            }
            for (int e = m; e < 4; e++) ent_key[c * 4 + e] = -1;
            if (m > mmax) mmax = m;
        }
        s_m = mmax;
    }
    if (t < NSLOT && blockIdx.x == 0) { g_t2_pre[t] = spre[t]; g_t2_rank[t] = srank[t]; }
    for (int j = t; j < NSLOT * 256; j += blockDim.x) shh[j] = 0;
    __syncthreads();

    int mm = s_m;
    if (mm > 0) {
        int stride = gridDim.x * blockDim.x;
        for (int g = blockIdx.x * blockDim.x + t; g < NG; g += stride) {
            uint4 p4 = ((const uint4*)g_packed)[g];
            unsigned pks[4] = { p4.x, p4.y, p4.z, p4.w };
#pragma unroll
            for (int k = 0; k < 4; k++) {
                unsigned pk = pks[k];
                int c = (int)(pk >> 29);
                unsigned bits = unpack_bits(pk);
                int key = (int)(bits >> 16);
                int b1 = (int)((bits >> 8) & 255u);
                for (int s = 0; s < mm; s++)
                    if (ent_key[c * 4 + s] == key)
                        atomicAdd(&shh[ent_slot[c * 4 + s] * 256 + b1], 1u);
            }
        }
    }
    __syncthreads();
    for (int j = t; j < NSLOT * 256; j += blockDim.x) {
        unsigned u = shh[j];
        if (u) atomicAdd(&g_hist2[j], u);
    }
}

// ---------------- K3: find3 prologue + level-3 histogram + last-block finalize ----
__global__ void k_hist3(const float* __restrict__ emin, const float* __restrict__ emax,
                        const unsigned char* __restrict__ einit) {
    __shared__ unsigned shh[NSLOT * 256];
    __shared__ int      sp[NSLOT];
    __shared__ int      sb[NSLOT];
    __shared__ unsigned sr[NSLOT];
    __shared__ int      ent_key[CD * 4];   // (pre<<8)|b1
    __shared__ int      ent_slot[CD * 4];
    __shared__ int      s_m;
    __shared__ unsigned sx[NSLOT];
    __shared__ bool     is_last;

    int t = threadIdx.x, lane = t & 31, warp = t >> 5;
    if (t < NSLOT) { sp[t] = g_t2_pre[t]; sb[t] = -1; sr[t] = 0; }
    __syncthreads();

    // find3: warp per unresolved slot, locate byte[15:8] in g_hist2
    for (int slot = warp; slot < NSLOT; slot += 8) {
        int pre = sp[slot];
        if (pre < 0 || pre == SPIKE_PRE) continue;
        int c4 = (slot >> 2) << 2;
        int src = slot;
        for (int j = 0; j < 4; j++) { if (sp[c4 + j] == pre) { src = c4 + j; break; } }
        unsigned rank = g_t2_rank[slot];
        unsigned h[8]; unsigned sum = 0;
#pragma unroll
        for (int j = 0; j < 8; j++) { h[j] = g_hist2[src * 256 + lane * 8 + j]; sum += h[j]; }
        unsigned v = sum;
        for (int off = 1; off < 32; off <<= 1) {
            unsigned u = __shfl_up_sync(0xffffffffu, v, off);
            if (lane >= off) v += u;
        }
        unsigned excl = v - sum;
        if (excl <= rank && rank < excl + sum) {
            unsigned run = excl;
#pragma unroll
            for (int j = 0; j < 8; j++) {
                if (rank < run + h[j]) { sb[slot] = lane * 8 + j; sr[slot] = rank - run; break; }
                run += h[j];
            }
        }
    }
    __syncthreads();
    if (t == 0) {
        int mmax = 0;
        for (int c = 0; c < CD; c++) {
            int m = 0;
            for (int j = 0; j < 4; j++) {
                int pre = sp[c * 4 + j];
                if (pre < 0 || pre == SPIKE_PRE) continue;
                int key = (pre << 8) | sb[c * 4 + j];
                bool dup = false;
                for (int j2 = 0; j2 < j; j2++) {
                    int pre2 = sp[c * 4 + j2];
                    if (pre2 >= 0 && pre2 != SPIKE_PRE && ((pre2 << 8) | sb[c * 4 + j2]) == key) { dup = true; break; }
                }
                if (!dup) { ent_key[c * 4 + m] = key; ent_slot[c * 4 + m] = c * 4 + j; m++; }
            }
            for (int e = m; e < 4; e++) ent_key[c * 4 + e] = -1;
            if (m > mmax) mmax = m;
        }
        s_m = mmax;
    }
    for (int j = t; j < NSLOT * 256; j += blockDim.x) shh[j] = 0;
    __syncthreads();

    int mm = s_m;
    if (mm > 0) {
        int stride = gridDim.x * blockDim.x;
        for (int g = blockIdx.x * blockDim.x + t; g < NG; g += stride) {
            uint4 p4 = ((const uint4*)g_packed)[g];
            unsigned pks[4] = { p4.x, p4.y, p4.z, p4.w };
#pragma unroll
            for (int k = 0; k < 4; k++) {
                unsigned pk = pks[k];
                int c = (int)(pk >> 29);
                unsigned bits = unpack_bits(pk);
                int key = (int)(bits >> 8);         // (pre<<8)|b1
                int b0 = (int)(bits & 255u);
                for (int s = 0; s < mm; s++)
                    if (ent_key[c * 4 + s] == key)
                        atomicAdd(&shh[ent_slot[c * 4 + s] * 256 + b0], 1u);
            }
        }
    }
    __syncthreads();
    for (int j = t; j < NSLOT * 256; j += blockDim.x) {
        unsigned u = shh[j];
        if (u) atomicAdd(&g_hist3[j], u);
    }

    // last-block finalize
    __threadfence();
    if (t == 0) is_last = (atomicAdd(&g_done, 1u) == (unsigned)(gridDim.x - 1));
    __syncthreads();
    if (!is_last) return;

    for (int slot = warp; slot < NSLOT; slot += 8) {
        int pre = sp[slot];
        if (pre < 0) continue;
        if (pre == SPIKE_PRE) { if (lane == 0) sx[slot] = 0x3F800000u; continue; }
        int key = (pre << 8) | sb[slot];
        int c4 = (slot >> 2) << 2;
        int src = slot;
        for (int j = 0; j < 4; j++) {
            int pre2 = sp[c4 + j];
            if (pre2 >= 0 && pre2 != SPIKE_PRE && ((pre2 << 8) | sb[c4 + j]) == key) { src = c4 + j; break; }
        }
        unsigned rank = sr[slot];
        unsigned h[8]; unsigned sum = 0;
#pragma unroll
        for (int j = 0; j < 8; j++) { h[j] = g_hist3[src * 256 + lane * 8 + j]; sum += h[j]; }
        unsigned v = sum;
        for (int off = 1; off < 32; off <<= 1) {
            unsigned u = __shfl_up_sync(0xffffffffu, v, off);
            if (lane >= off) v += u;
        }
        unsigned excl = v - sum;
        if (excl <= rank && rank < excl + sum) {
            unsigned run = excl;
#pragma unroll
            for (int j = 0; j < 8; j++) {
                if (rank < run + h[j]) {
                    sx[slot] = ((unsigned)pre << 16) | ((unsigned)sb[slot] << 8) | (unsigned)(lane * 8 + j);
                    break;
                }
                run += h[j];
            }
        }
    }
    __syncthreads();
    if (t < CD) {
        int c = t;
        float nmin, nmax;
        if (g_n[c] == 0) {
            nmin = emin[c]; nmax = emax[c];
        } else {
            float x0 = __uint_as_float(sx[c * 4 + 0]);
            float x1 = __uint_as_float(sx[c * 4 + 1]);
            float x2 = __uint_as_float(sx[c * 4 + 2]);
            float x3 = __uint_as_float(sx[c * 4 + 3]);
            float bmin = (float)((double)x0 + g_g05[c] * ((double)x1 - (double)x0));
            float bmax = (float)((double)x2 + g_g95[c] * ((double)x3 - (double)x2));
            bool ini = einit[c] != 0;
            nmin = ini ? (0.99f * emin[c] + 0.01f * bmin) : bmin;
            nmax = ini ? (0.99f * emax[c] + 0.01f * bmax) : bmax;
        }
        g_newmin[c] = nmin; g_newmax[c] = nmax;
    }
}

// ---------------- K4: gamma map + feature scaling (HBM-bound) ----------------
__global__ void k_scale(const float4* __restrict__ ft, const float* __restrict__ ranks,
                        float* __restrict__ out) {
    __shared__ float smin[CD], sinv[CD], sadd[CD], smax[CD], sint[CD];
    if (threadIdx.x < CD) {
        int c = threadIdx.x;
        float mn = g_newmin[c], mx = g_newmax[c];
        smin[c] = mn; smax[c] = mx;
        sint[c] = 1.0f - ranks[c] / 4.0f;
        if (mx > mn) { sinv[c] = 1.0f / (mx - mn + 1e-8f); sadd[c] = 0.0f; }
        else         { sinv[c] = 0.0f;                     sadd[c] = 0.5f; }
    }
    __syncthreads();
    int g = blockIdx.x * blockDim.x + threadIdx.x;
    if (g >= NG) return;
    uint4 p4 = ((const uint4*)g_packed)[g];
    unsigned pks[4] = { p4.x, p4.y, p4.z, p4.w };

    float gm[4];
#pragma unroll
    for (int k = 0; k < 4; k++) {
        unsigned pk = pks[k];
        int c = (int)(pk >> 29);
        float cv = __uint_as_float(unpack_bits(pk));
        float mn = smin[c], mx = smax[c];
        float cl = fminf(fmaxf(cv, mn), mx);
        float nr = (cl - mn) * sinv[c] + sadd[c];
        gm[k] = 1.0f + sint[c] * (1.0f + 0.5f * (1.0f - nr));
    }
    __stcs((float4*)(out + NFEAT) + g, make_float4(gm[0], gm[1], gm[2], gm[3]));

    int v = g * 4;
    int b = (v >= DHW) ? 1 : 0;
    int s4 = g - b * Q4;
    size_t fbase = (size_t)(b * FD) * Q4 + (size_t)s4;
    float4* o4 = (float4*)out;
#pragma unroll 8
    for (int f = 0; f < FD; f++) {
        float4 x = __ldcs(&ft[fbase + (size_t)f * Q4]);
        x.x *= gm[0]; x.y *= gm[1]; x.z *= gm[2]; x.w *= gm[3];
        __stcs(&o4[fbase + (size_t)f * Q4], x);
    }
}

// ---------------- launch ----------------
extern "C" void kernel_launch(void* const* d_in, const int* in_sizes, int n_in,
                              void* d_out, int out_size) {
    const float* feat          = (const float*)d_in[0];
    const float* logits        = (const float*)d_in[1];
    const int*   labels        = (const int*)d_in[2];
    const float* ranks         = (const float*)d_in[3];
    const float* emin          = (const float*)d_in[4];
    const float* emax          = (const float*)d_in[5];
    const unsigned char* einit = (const unsigned char*)d_in[6];
    float* out = (float*)d_out;
    (void)in_sizes; (void)n_in; (void)out_size;

    k_zero<<<16, 256>>>();
    k_conf<<<HGRID, 256>>>((const float4*)logits, (const int4*)labels);
    k_hist2<<<HGRID, 256>>>();
    k_hist3<<<HGRID, 256>>>(emin, emax, einit);
    k_scale<<<(NG + 255) / 256, 256>>>((const float4*)feat, ranks, out);
}

// round 9
// speedup vs baseline: 1.0309x; 1.0309x over previous
#include <cuda_runtime.h>

// Fixed problem shapes
#define BD 2
#define FD 32
#define CD 5
#define DHW 884736           // 96^3
#define Q4 (DHW/4)           // 221184
#define NVOX (BD*DHW)        // 1769472
#define NG (NVOX/4)          // 442368
#define NFEAT (BD*FD*DHW)    // 56623104
#define PLO 15872            // conf in (0.19,1.0+] -> 16-bit prefix within [PLO, PLO+512)
#define NBIN 512
#define NSLOT 20             // 5 classes x 4 order statistics
#define NENT 20              // compacted refinement entries (<=4 per class)
#define SPIKE_PRE 16256      // 0x3F80 : bin containing only conf == 1.0 (+/- 1ulp)
#define HGRID 592

// ---------------- device scratch ----------------
__device__ __align__(16) unsigned g_packed[NVOX];        // label<<29 | (conf bits & 0x1FFFFFFF)
__device__ unsigned g_hist1[CD * NBIN];
__device__ __align__(16) unsigned g_histF[NENT * 65536]; // fine 16-bit histograms, 5.24 MB
__device__ int      g_t2_pre[NSLOT];
__device__ unsigned g_t2_rank[NSLOT];
__device__ int      g_ent_key[NENT];                     // 13-bit reduced prefix, -1 = unused
__device__ unsigned g_xbits[NSLOT];
__device__ unsigned g_n[CD];
__device__ double   g_g05[CD], g_g95[CD];
__device__ float    g_newmin[CD], g_newmax[CD];
__device__ unsigned g_done;

// ---------------- K0: zero scratch (every replay) ----------------
__global__ void k_zero() {
    int i = blockIdx.x * blockDim.x + threadIdx.x;
    int stride = gridDim.x * blockDim.x;
    uint4 z = make_uint4(0, 0, 0, 0);
    for (int j = i; j < (NENT * 65536) / 4; j += stride) ((uint4*)g_histF)[j] = z;
    for (int j = i; j < CD * NBIN; j += stride) g_hist1[j] = 0;
    if (i == 0) g_done = 0;
}

// ---------------- K1: confidence + packed store + level-1 histogram ----------------
__device__ __forceinline__ float conf5(float a, float b, float c, float d, float e) {
    float y0 = a * 10.0f, y1 = b * 10.0f, y2 = c * 10.0f, y3 = d * 10.0f, y4 = e * 10.0f;
    float m = fmaxf(fmaxf(fmaxf(y0, y1), fmaxf(y2, y3)), y4);
    float s = __expf(y0 - m) + __expf(y1 - m) + __expf(y2 - m) + __expf(y3 - m) + __expf(y4 - m);
    return __fdividef(1.0f, s);
}

__global__ void k_conf(const float4* __restrict__ lg, const int4* __restrict__ lb) {
    __shared__ unsigned sh[CD * NBIN];
    for (int j = threadIdx.x; j < CD * NBIN; j += blockDim.x) sh[j] = 0;
    __syncthreads();
    int stride = gridDim.x * blockDim.x;
    for (int g = blockIdx.x * blockDim.x + threadIdx.x; g < NG; g += stride) {
        int v = g * 4;
        int b = (v >= DHW) ? 1 : 0;
        int s4 = g - b * Q4;
        size_t base = (size_t)(b * CD) * Q4 + (size_t)s4;
        float4 L0 = __ldcs(&lg[base]);
        float4 L1 = __ldcs(&lg[base + Q4]);
        float4 L2 = __ldcs(&lg[base + 2 * (size_t)Q4]);
        float4 L3 = __ldcs(&lg[base + 3 * (size_t)Q4]);
        float4 L4 = __ldcs(&lg[base + 4 * (size_t)Q4]);
        float cf[4];
        cf[0] = conf5(L0.x, L1.x, L2.x, L3.x, L4.x);
        cf[1] = conf5(L0.y, L1.y, L2.y, L3.y, L4.y);
        cf[2] = conf5(L0.z, L1.z, L2.z, L3.z, L4.z);
        cf[3] = conf5(L0.w, L1.w, L2.w, L3.w, L4.w);
        int4 li = __ldcs(&lb[g]);
        int cc[4] = { li.x, li.y, li.z, li.w };
        unsigned pk[4];
#pragma unroll
        for (int k = 0; k < 4; k++) {
            unsigned bits = __float_as_uint(cf[k]);
            pk[k] = ((unsigned)cc[k] << 29) | (bits & 0x1FFFFFFFu);
            unsigned idx = (bits >> 16) - PLO;
            if (idx < NBIN) atomicAdd(&sh[cc[k] * NBIN + idx], 1u);
        }
        __stcs((uint4*)g_packed + g, make_uint4(pk[0], pk[1], pk[2], pk[3]));
    }
    __syncthreads();
    for (int j = threadIdx.x; j < CD * NBIN; j += blockDim.x) {
        unsigned u = sh[j];
        if (u) atomicAdd(&g_hist1[j], u);
    }
}

// ---------------- K2: find2 prologue + ONE fine-histogram pass over packed -------
__global__ void k_fine() {
    __shared__ int      spre[NSLOT];
    __shared__ unsigned srank[NSLOT];
    __shared__ int      sek[NENT];
    __shared__ int      s_m;
    __shared__ unsigned swsum[8], swpre[8];
    __shared__ unsigned s_n;

    int t = threadIdx.x, lane = t & 31, warp = t >> 5;
    if (t < NSLOT) { spre[t] = -1; srank[t] = 0; }
    __syncthreads();

    // find2: scan 512-bin prefix histogram per class (2 bins/thread)
    for (int c = 0; c < CD; c++) {
        unsigned a = g_hist1[c * NBIN + 2 * t];
        unsigned b = g_hist1[c * NBIN + 2 * t + 1];
        unsigned s = a + b;
        unsigned incl = s;
        for (int off = 1; off < 32; off <<= 1) {
            unsigned u = __shfl_up_sync(0xffffffffu, incl, off);
            if (lane >= off) incl += u;
        }
        if (lane == 31) swsum[warp] = incl;
        __syncthreads();
        if (t == 0) {
            unsigned run = 0;
#pragma unroll
            for (int w = 0; w < 8; w++) { swpre[w] = run; run += swsum[w]; }
            s_n = run;
        }
        __syncthreads();
        unsigned total = s_n;
        long long exclp = (long long)(incl - s + swpre[warp]);
        long long n = (long long)total;
        if (n == 0) {
            if (t == 0 && blockIdx.x == 0) { g_n[c] = 0; g_g05[c] = 0.0; g_g95[c] = 0.0; }
        } else {
            double p05 = 0.05 * (double)(n - 1);
            long long i05 = (long long)p05;
            double p95 = 0.95 * (double)(n - 1);
            long long i95 = (long long)p95;
            if (t == 0 && blockIdx.x == 0) {
                g_n[c] = total;
                g_g05[c] = p05 - (double)i05;
                g_g95[c] = p95 - (double)i95;
            }
            long long rr[4];
            rr[0] = i05; rr[1] = (i05 + 1 < n) ? i05 + 1 : i05;
            rr[2] = i95; rr[3] = (i95 + 1 < n) ? i95 + 1 : i95;
#pragma unroll
            for (int j = 0; j < 4; j++) {
                long long r = rr[j];
                if (r >= exclp && r < exclp + (long long)s) {
                    unsigned rem = (unsigned)(r - exclp);
                    if (rem < a) { spre[c * 4 + j] = PLO + 2 * t;     srank[c * 4 + j] = rem; }
                    else         { spre[c * 4 + j] = PLO + 2 * t + 1; srank[c * 4 + j] = rem - a; }
                }
            }
        }
        __syncthreads();
    }
    // Compact entry list: per class, dedup non-spike prefixes
    if (t == 0) {
        int mmax = 0;
        for (int c = 0; c < CD; c++) {
            int m = 0;
            for (int j = 0; j < 4; j++) {
                int pre = spre[c * 4 + j];
                if (pre < 0 || pre == SPIKE_PRE) continue;
                bool dup = false;
                for (int j2 = 0; j2 < j; j2++) if (spre[c * 4 + j2] == pre) { dup = true; break; }
                if (!dup) { sek[c * 4 + m] = pre & 0x1FFF; m++; }
            }
            for (int e = m; e < 4; e++) sek[c * 4 + e] = -1;
            if (m > mmax) mmax = m;
        }
        s_m = mmax;
    }
    __syncthreads();
    if (t < NSLOT && blockIdx.x == 0) {
        g_t2_pre[t] = spre[t]; g_t2_rank[t] = srank[t]; g_ent_key[t] = sek[t];
    }

    int mm = s_m;
    if (mm > 0) {
        int stride = gridDim.x * blockDim.x;
        for (int g = blockIdx.x * blockDim.x + t; g < NG; g += stride) {
            uint4 p4 = ((const uint4*)g_packed)[g];
            unsigned pks[4] = { p4.x, p4.y, p4.z, p4.w };
#pragma unroll
            for (int k = 0; k < 4; k++) {
                unsigned pk = pks[k];
                int c = (int)(pk >> 29);
                int key = (int)((pk >> 16) & 0x1FFFu);
                for (int s = 0; s < mm; s++)
                    if (sek[c * 4 + s] == key)
                        atomicAdd(&g_histF[(c * 4 + s) * 65536 + (pk & 0xFFFFu)], 1u); // RED
            }
        }
    }
}

// ---------------- K3: block per slot: exact order stat from fine hist + finalize --
__global__ void k_select(const float* __restrict__ emin, const float* __restrict__ emax,
                         const unsigned char* __restrict__ einit) {   // 20 blocks x 256
    __shared__ unsigned csum[256];
    __shared__ unsigned wsum[8];
    __shared__ int s_jc; __shared__ unsigned s_rem;
    __shared__ unsigned s_xb;
    __shared__ bool is_last;

    int slot = blockIdx.x;
    int t = threadIdx.x, lane = t & 31, warp = t >> 5;
    int pre = g_t2_pre[slot];
    if (t == 0) s_xb = 0x3F800000u;       // default: spike / empty-class
    __syncthreads();

    if (pre >= 0 && pre != SPIKE_PRE) {
        int c = slot >> 2;
        int key = pre & 0x1FFF;
        int e = c * 4;
        for (int s = 0; s < 4; s++) if (g_ent_key[c * 4 + s] == key) { e = c * 4 + s; break; }
        const unsigned* hf = &g_histF[e * 65536];
        // chunk sums: 256 chunks of 256 bins; warp w handles chunks w, w+8, ...
        for (int j = warp; j < 256; j += 8) {
            unsigned ss = 0;
            for (int i = lane; i < 256; i += 32) ss += hf[j * 256 + i];
            for (int off = 16; off; off >>= 1) ss += __shfl_down_sync(0xffffffffu, ss, off);
            if (lane == 0) csum[j] = ss;
        }
        __syncthreads();
        // block inclusive scan of 256 chunk sums
        unsigned v = csum[t];
        unsigned incl = v;
        for (int off = 1; off < 32; off <<= 1) {
            unsigned u = __shfl_up_sync(0xffffffffu, incl, off);
            if (lane >= off) incl += u;
        }
        if (lane == 31) wsum[warp] = incl;
        __syncthreads();
        unsigned wpre = 0;
        for (int w = 0; w < warp; w++) wpre += wsum[w];
        unsigned inclb = incl + wpre;
        unsigned rank = g_t2_rank[slot];
        unsigned exclb = inclb - v;
        if (exclb <= rank && rank < inclb) { s_jc = t; s_rem = rank - exclb; }
        __syncthreads();
        int jc = s_jc; unsigned rem = s_rem;
        if (warp == 0) {
            unsigned h[8]; unsigned sum = 0;
#pragma unroll
            for (int j = 0; j < 8; j++) { h[j] = hf[jc * 256 + lane * 8 + j]; sum += h[j]; }
            unsigned vv = sum;
            for (int off = 1; off < 32; off <<= 1) {
                unsigned u = __shfl_up_sync(0xffffffffu, vv, off);
                if (lane >= off) vv += u;
            }
            unsigned excl = vv - sum;
            if (excl <= rem && rem < excl + sum) {
                unsigned run = excl;
#pragma unroll
                for (int j = 0; j < 8; j++) {
                    if (rem < run + h[j]) {
                        s_xb = ((unsigned)pre << 16) | (unsigned)(jc * 256 + lane * 8 + j);
                        break;
                    }
                    run += h[j];
                }
            }
        }
    }
    __syncthreads();
    if (t == 0) {
        g_xbits[slot] = s_xb;
        __threadfence();
        is_last = (atomicAdd(&g_done, 1u) == (unsigned)(gridDim.x - 1));
    }
    __syncthreads();
    if (!is_last) return;

    if (t < CD) {
        int c = t;
        float nmin, nmax;
        if (g_n[c] == 0) {
            nmin = emin[c]; nmax = emax[c];
        } else {
            float x0 = __uint_as_float(g_xbits[c * 4 + 0]);
            float x1 = __uint_as_float(g_xbits[c * 4 + 1]);
            float x2 = __uint_as_float(g_xbits[c * 4 + 2]);
            float x3 = __uint_as_float(g_xbits[c * 4 + 3]);
            float bmin = (float)((double)x0 + g_g05[c] * ((double)x1 - (double)x0));
            float bmax = (float)((double)x2 + g_g95[c] * ((double)x3 - (double)x2));
            bool ini = einit[c] != 0;
            nmin = ini ? (0.99f * emin[c] + 0.01f * bmin) : bmin;
            nmax = ini ? (0.99f * emax[c] + 0.01f * bmax) : bmax;
        }
        g_newmin[c] = nmin; g_newmax[c] = nmax;
    }
}

// ---------------- K4: gamma map + feature scaling (HBM-bound) ----------------
__global__ void k_scale(const float4* __restrict__ ft, const float* __restrict__ ranks,
                        float* __restrict__ out) {
    __shared__ float smin[CD], sinv[CD], sadd[CD], smax[CD], sint[CD];
    if (threadIdx.x < CD) {
        int c = threadIdx.x;
        float mn = g_newmin[c], mx = g_newmax[c];
        smin[c] = mn; smax[c] = mx;
        sint[c] = 1.0f - ranks[c] / 4.0f;
        if (mx > mn) { sinv[c] = 1.0f / (mx - mn + 1e-8f); sadd[c] = 0.0f; }
        else         { sinv[c] = 0.0f;                     sadd[c] = 0.5f; }
    }
    __syncthreads();
    int g = blockIdx.x * blockDim.x + threadIdx.x;
    if (g >= NG) return;
    uint4 p4 = ((const uint4*)g_packed)[g];
    unsigned pks[4] = { p4.x, p4.y, p4.z, p4.w };

    float gm[4];
#pragma unroll
    for (int k = 0; k < 4; k++) {
        unsigned pk = pks[k];
        int c = (int)(pk >> 29);
        float cv = __uint_as_float((pk & 0x1FFFFFFFu) | 0x20000000u);
        float mn = smin[c], mx = smax[c];
        float cl = fminf(fmaxf(cv, mn), mx);
        float nr = (cl - mn) * sinv[c] + sadd[c];
        gm[k] = 1.0f + sint[c] * (1.0f + 0.5f * (1.0f - nr));
    }
    __stcs((float4*)(out + NFEAT) + g, make_float4(gm[0], gm[1], gm[2], gm[3]));

    int v = g * 4;
    int b = (v >= DHW) ? 1 : 0;
    int s4 = g - b * Q4;
    size_t fbase = (size_t)(b * FD) * Q4 + (size_t)s4;
    float4* o4 = (float4*)out;
#pragma unroll 8
    for (int f = 0; f < FD; f++) {
        float4 x = __ldcs(&ft[fbase + (size_t)f * Q4]);
        x.x *= gm[0]; x.y *= gm[1]; x.z *= gm[2]; x.w *= gm[3];
        __stcs(&o4[fbase + (size_t)f * Q4], x);
    }
}

// ---------------- launch ----------------
extern "C" void kernel_launch(void* const* d_in, const int* in_sizes, int n_in,
                              void* d_out, int out_size) {
    const float* feat          = (const float*)d_in[0];
    const float* logits        = (const float*)d_in[1];
    const int*   labels        = (const int*)d_in[2];
    const float* ranks         = (const float*)d_in[3];
    const float* emin          = (const float*)d_in[4];
    const float* emax          = (const float*)d_in[5];
    const unsigned char* einit = (const unsigned char*)d_in[6];
    float* out = (float*)d_out;
    (void)in_sizes; (void)n_in; (void)out_size;

    k_zero<<<HGRID, 256>>>();
    k_conf<<<HGRID, 256>>>((const float4*)logits, (const int4*)labels);
    k_fine<<<HGRID, 256>>>();
    k_select<<<NSLOT, 256>>>(emin, emax, einit);
    k_scale<<<(NG + 255) / 256, 256>>>((const float4*)feat, ranks, out);
}

// round 10
// speedup vs baseline: 1.1316x; 1.0977x over previous
#include <cuda_runtime.h>

// Fixed problem shapes
#define BD 2
#define FD 32
#define CD 5
#define DHW 884736           // 96^3
#define Q4 (DHW/4)           // 221184
#define NVOX (BD*DHW)        // 1769472
#define NG (NVOX/4)          // 442368
#define NFEAT (BD*FD*DHW)    // 56623104
#define PLO 15872            // conf in (0.19,1.0] -> 16-bit prefix within [PLO, PLO+512)
#define NBIN 512
#define NSLOT 20             // 5 classes x 4 order statistics
#define NENT 20
#define SPIKE_PRE 16256      // 0x3F80 : bin containing only conf == 1.0
#define HGRID 592

// ---------------- device scratch ----------------
__device__ __align__(16) unsigned g_packed[NVOX];        // label<<29 | (conf bits & 0x1FFFFFFF)
__device__ unsigned g_hist1[CD * NBIN];
__device__ __align__(16) unsigned g_histF[NENT * 65536]; // fine 16-bit histograms (5.24 MB)
__device__ __align__(16) unsigned g_chunk[NENT * 256];   // 256-chunk sums per entry
__device__ float    g_newmin[CD], g_newmax[CD];
__device__ unsigned g_done;

// ---------------- K0: zero scratch (every replay) ----------------
__global__ void k_zero() {
    int i = blockIdx.x * blockDim.x + threadIdx.x;
    int stride = gridDim.x * blockDim.x;
    uint4 z = make_uint4(0, 0, 0, 0);
    for (int j = i; j < (NENT * 65536) / 4; j += stride) ((uint4*)g_histF)[j] = z;
    for (int j = i; j < (NENT * 256) / 4; j += stride)   ((uint4*)g_chunk)[j] = z;
    for (int j = i; j < CD * NBIN; j += stride) g_hist1[j] = 0;
    if (i == 0) g_done = 0;
}

// ---------------- K1: confidence + packed store + level-1 histogram ----------------
__device__ __forceinline__ float conf5(float a, float b, float c, float d, float e) {
    float y0 = a * 10.0f, y1 = b * 10.0f, y2 = c * 10.0f, y3 = d * 10.0f, y4 = e * 10.0f;
    float m = fmaxf(fmaxf(fmaxf(y0, y1), fmaxf(y2, y3)), y4);
    float s = __expf(y0 - m) + __expf(y1 - m) + __expf(y2 - m) + __expf(y3 - m) + __expf(y4 - m);
    return __fdividef(1.0f, s);
}

__global__ void k_conf(const float4* __restrict__ lg, const int4* __restrict__ lb) {
    __shared__ unsigned sh[CD * NBIN];
    for (int j = threadIdx.x; j < CD * NBIN; j += blockDim.x) sh[j] = 0;
    __syncthreads();
    int stride = gridDim.x * blockDim.x;
    for (int g = blockIdx.x * blockDim.x + threadIdx.x; g < NG; g += stride) {
        int v = g * 4;
        int b = (v >= DHW) ? 1 : 0;
        int s4 = g - b * Q4;
        size_t base = (size_t)(b * CD) * Q4 + (size_t)s4;
        float4 L0 = __ldcs(&lg[base]);
        float4 L1 = __ldcs(&lg[base + Q4]);
        float4 L2 = __ldcs(&lg[base + 2 * (size_t)Q4]);
        float4 L3 = __ldcs(&lg[base + 3 * (size_t)Q4]);
        float4 L4 = __ldcs(&lg[base + 4 * (size_t)Q4]);
        float cf[4];
        cf[0] = conf5(L0.x, L1.x, L2.x, L3.x, L4.x);
        cf[1] = conf5(L0.y, L1.y, L2.y, L3.y, L4.y);
        cf[2] = conf5(L0.z, L1.z, L2.z, L3.z, L4.z);
        cf[3] = conf5(L0.w, L1.w, L2.w, L3.w, L4.w);
        int4 li = __ldcs(&lb[g]);
        int cc[4] = { li.x, li.y, li.z, li.w };
        unsigned pk[4];
#pragma unroll
        for (int k = 0; k < 4; k++) {
            unsigned bits = __float_as_uint(cf[k]);
            pk[k] = ((unsigned)cc[k] << 29) | (bits & 0x1FFFFFFFu);
            unsigned idx = (bits >> 16) - PLO;
            if (idx < NBIN) atomicAdd(&sh[cc[k] * NBIN + idx], 1u);
        }
        __stcs((uint4*)g_packed + g, make_uint4(pk[0], pk[1], pk[2], pk[3]));
    }
    __syncthreads();
    for (int j = threadIdx.x; j < CD * NBIN; j += blockDim.x) {
        unsigned u = sh[j];
        if (u) atomicAdd(&g_hist1[j], u);
    }
}

// ---------------- K2: find2 + fine-histogram pass + last-block select/finalize -----
__global__ void k_fine(const float* __restrict__ emin, const float* __restrict__ emax,
                       const unsigned char* __restrict__ einit) {
    __shared__ int      spre[NSLOT];
    __shared__ unsigned srank[NSLOT];
    __shared__ int      sek[NENT];
    __shared__ int      s_m;
    __shared__ unsigned swsum[8], swpre[8];
    __shared__ unsigned s_n;
    __shared__ unsigned s_ncls[CD];
    __shared__ double   s_f05[CD], s_f95[CD];
    __shared__ unsigned sx[NSLOT];
    __shared__ bool     is_last;

    int t = threadIdx.x, lane = t & 31, warp = t >> 5;
    if (t < NSLOT) { spre[t] = -1; srank[t] = 0; }
    __syncthreads();

    // ---- find2: scan 512-bin prefix histogram per class (2 bins/thread) ----
    for (int c = 0; c < CD; c++) {
        unsigned a = g_hist1[c * NBIN + 2 * t];
        unsigned b = g_hist1[c * NBIN + 2 * t + 1];
        unsigned s = a + b;
        unsigned incl = s;
        for (int off = 1; off < 32; off <<= 1) {
            unsigned u = __shfl_up_sync(0xffffffffu, incl, off);
            if (lane >= off) incl += u;
        }
        if (lane == 31) swsum[warp] = incl;
        __syncthreads();
        if (t == 0) {
            unsigned run = 0;
#pragma unroll
            for (int w = 0; w < 8; w++) { swpre[w] = run; run += swsum[w]; }
            s_n = run;
        }
        __syncthreads();
        unsigned total = s_n;
        long long exclp = (long long)(incl - s + swpre[warp]);
        long long n = (long long)total;
        if (n == 0) {
            if (t == 0) { s_ncls[c] = 0; s_f05[c] = 0.0; s_f95[c] = 0.0; }
        } else {
            double p05 = 0.05 * (double)(n - 1);
            long long i05 = (long long)p05;
            double p95 = 0.95 * (double)(n - 1);
            long long i95 = (long long)p95;
            if (t == 0) {
                s_ncls[c] = total;
                s_f05[c] = p05 - (double)i05;
                s_f95[c] = p95 - (double)i95;
            }
            long long rr[4];
            rr[0] = i05; rr[1] = (i05 + 1 < n) ? i05 + 1 : i05;
            rr[2] = i95; rr[3] = (i95 + 1 < n) ? i95 + 1 : i95;
#pragma unroll
            for (int j = 0; j < 4; j++) {
                long long r = rr[j];
                if (r >= exclp && r < exclp + (long long)s) {
                    unsigned rem = (unsigned)(r - exclp);
                    if (rem < a) { spre[c * 4 + j] = PLO + 2 * t;     srank[c * 4 + j] = rem; }
                    else         { spre[c * 4 + j] = PLO + 2 * t + 1; srank[c * 4 + j] = rem - a; }
                }
            }
        }
        __syncthreads();
    }
    // compact entry list: dedup non-spike prefixes per class
    if (t == 0) {
        int mmax = 0;
        for (int c = 0; c < CD; c++) {
            int m = 0;
            for (int j = 0; j < 4; j++) {
                int pre = spre[c * 4 + j];
                if (pre < 0 || pre == SPIKE_PRE) continue;
                bool dup = false;
                for (int j2 = 0; j2 < j; j2++) if (spre[c * 4 + j2] == pre) { dup = true; break; }
                if (!dup) { sek[c * 4 + m] = pre & 0x1FFF; m++; }
            }
            for (int e = m; e < 4; e++) sek[c * 4 + e] = -1;
            if (m > mmax) mmax = m;
        }
        s_m = mmax;
    }
    __syncthreads();

    // ---- fine pass: 16-bit histogram + 256-chunk sums for matching entries ----
    int mm = s_m;
    if (mm > 0) {
        int stride = gridDim.x * blockDim.x;
        for (int g = blockIdx.x * blockDim.x + t; g < NG; g += stride) {
            uint4 p4 = ((const uint4*)g_packed)[g];
            unsigned pks[4] = { p4.x, p4.y, p4.z, p4.w };
#pragma unroll
            for (int k = 0; k < 4; k++) {
                unsigned pk = pks[k];
                int c = (int)(pk >> 29);
                int key = (int)((pk >> 16) & 0x1FFFu);
                for (int s = 0; s < mm; s++)
                    if (sek[c * 4 + s] == key) {
                        unsigned low = pk & 0xFFFFu;
                        atomicAdd(&g_histF[(c * 4 + s) * 65536 + low], 1u);
                        atomicAdd(&g_chunk[(c * 4 + s) * 256 + (low >> 8)], 1u);
                    }
            }
        }
    }

    // ---- last-block: select order statistics via chunk sums, then EMA finalize ----
    __threadfence();
    if (t == 0) is_last = (atomicAdd(&g_done, 1u) == (unsigned)(gridDim.x - 1));
    __syncthreads();
    if (!is_last) return;

    for (int slot = warp; slot < NSLOT; slot += 8) {
        int pre = spre[slot];
        if (pre < 0 || pre == SPIKE_PRE) {
            if (lane == 0) sx[slot] = 0x3F800000u;   // spike or empty class
            continue;
        }
        int c = slot >> 2;
        int key = pre & 0x1FFF;
        int e = c * 4;
        for (int s = 0; s < 4; s++) if (sek[c * 4 + s] == key) { e = c * 4 + s; break; }
        const unsigned* hc = &g_chunk[e * 256];
        const unsigned* hf = &g_histF[e * 65536];
        unsigned rank = srank[slot];

        // scan 256 chunk sums (8 per lane)
        unsigned h[8]; unsigned sum = 0;
#pragma unroll
        for (int j = 0; j < 8; j++) { h[j] = hc[lane * 8 + j]; sum += h[j]; }
        unsigned v = sum;
        for (int off = 1; off < 32; off <<= 1) {
            unsigned u = __shfl_up_sync(0xffffffffu, v, off);
            if (lane >= off) v += u;
        }
        unsigned excl = v - sum;
        bool hit = (excl <= rank && rank < excl + sum);
        unsigned mball = __ballot_sync(0xffffffffu, hit);
        int srcl = __ffs(mball) - 1;
        int jc = 0; unsigned rem = 0;
        if (hit) {
            unsigned run = excl;
#pragma unroll
            for (int j = 0; j < 8; j++) {
                if (rank < run + h[j]) { jc = lane * 8 + j; rem = rank - run; break; }
                run += h[j];
            }
        }
        jc  = __shfl_sync(0xffffffffu, jc, srcl);
        rem = __shfl_sync(0xffffffffu, rem, srcl);

        // drill into chunk jc (256 fine bins, 8 per lane)
        unsigned f[8]; unsigned fsum = 0;
#pragma unroll
        for (int j = 0; j < 8; j++) { f[j] = hf[jc * 256 + lane * 8 + j]; fsum += f[j]; }
        unsigned fv = fsum;
        for (int off = 1; off < 32; off <<= 1) {
            unsigned u = __shfl_up_sync(0xffffffffu, fv, off);
            if (lane >= off) fv += u;
        }
        unsigned fexcl = fv - fsum;
        if (fexcl <= rem && rem < fexcl + fsum) {
            unsigned run = fexcl;
#pragma unroll
            for (int j = 0; j < 8; j++) {
                if (rem < run + f[j]) {
                    sx[slot] = ((unsigned)pre << 16) | (unsigned)(jc * 256 + lane * 8 + j);
                    break;
                }
                run += f[j];
            }
        }
    }
    __syncthreads();
    if (t < CD) {
        int c = t;
        float nmin, nmax;
        if (s_ncls[c] == 0) {
            nmin = emin[c]; nmax = emax[c];
        } else {
            float x0 = __uint_as_float(sx[c * 4 + 0]);
            float x1 = __uint_as_float(sx[c * 4 + 1]);
            float x2 = __uint_as_float(sx[c * 4 + 2]);
            float x3 = __uint_as_float(sx[c * 4 + 3]);
            float bmin = (float)((double)x0 + s_f05[c] * ((double)x1 - (double)x0));
            float bmax = (float)((double)x2 + s_f95[c] * ((double)x3 - (double)x2));
            bool ini = einit[c] != 0;
            nmin = ini ? (0.99f * emin[c] + 0.01f * bmin) : bmin;
            nmax = ini ? (0.99f * emax[c] + 0.01f * bmax) : bmax;
        }
        g_newmin[c] = nmin; g_newmax[c] = nmax;
    }
}

// ---------------- K3: gamma map + feature scaling (HBM-bound) ----------------
__global__ void k_scale(const float4* __restrict__ ft, const float* __restrict__ ranks,
                        float* __restrict__ out) {
    __shared__ float smin[CD], sinv[CD], sadd[CD], smax[CD], sint[CD];
    if (threadIdx.x < CD) {
        int c = threadIdx.x;
        float mn = g_newmin[c], mx = g_newmax[c];
        smin[c] = mn; smax[c] = mx;
        sint[c] = 1.0f - ranks[c] / 4.0f;
        if (mx > mn) { sinv[c] = 1.0f / (mx - mn + 1e-8f); sadd[c] = 0.0f; }
        else         { sinv[c] = 0.0f;                     sadd[c] = 0.5f; }
    }
    __syncthreads();
    int g = blockIdx.x * blockDim.x + threadIdx.x;
    if (g >= NG) return;
    uint4 p4 = ((const uint4*)g_packed)[g];
    unsigned pks[4] = { p4.x, p4.y, p4.z, p4.w };

    float gm[4];
#pragma unroll
    for (int k = 0; k < 4; k++) {
        unsigned pk = pks[k];
        int c = (int)(pk >> 29);
        float cv = __uint_as_float((pk & 0x1FFFFFFFu) | 0x20000000u);
        float mn = smin[c], mx = smax[c];
        float cl = fminf(fmaxf(cv, mn), mx);
        float nr = (cl - mn) * sinv[c] + sadd[c];
        gm[k] = 1.0f + sint[c] * (1.0f + 0.5f * (1.0f - nr));
    }
    __stcs((float4*)(out + NFEAT) + g, make_float4(gm[0], gm[1], gm[2], gm[3]));

    int v = g * 4;
    int b = (v >= DHW) ? 1 : 0;
    int s4 = g - b * Q4;
    size_t fbase = (size_t)(b * FD) * Q4 + (size_t)s4;
    float4* o4 = (float4*)out;
#pragma unroll 8
    for (int f = 0; f < FD; f++) {
        float4 x = __ldcs(&ft[fbase + (size_t)f * Q4]);
        x.x *= gm[0]; x.y *= gm[1]; x.z *= gm[2]; x.w *= gm[3];
        __stcs(&o4[fbase + (size_t)f * Q4], x);
    }
}

// ---------------- launch ----------------
extern "C" void kernel_launch(void* const* d_in, const int* in_sizes, int n_in,
                              void* d_out, int out_size) {
    const float* feat          = (const float*)d_in[0];
    const float* logits        = (const float*)d_in[1];
    const int*   labels        = (const int*)d_in[2];
    const float* ranks         = (const float*)d_in[3];
    const float* emin          = (const float*)d_in[4];
    const float* emax          = (const float*)d_in[5];
    const unsigned char* einit = (const unsigned char*)d_in[6];
    float* out = (float*)d_out;
    (void)in_sizes; (void)n_in; (void)out_size;

    k_zero<<<HGRID, 256>>>();
    k_conf<<<HGRID, 256>>>((const float4*)logits, (const int4*)labels);
    k_fine<<<HGRID, 256>>>(emin, emax, einit);
    k_scale<<<(NG + 255) / 256, 256>>>((const float4*)feat, ranks, out);
}

// round 12
// speedup vs baseline: 1.1950x; 1.0560x over previous
#include <cuda_runtime.h>

// Fixed problem shapes
#define BD 2
#define FD 32
#define CD 5
#define DHW 884736           // 96^3
#define Q4 (DHW/4)           // 221184 (= 432 * 512)
#define NVOX (BD*DHW)        // 1769472
#define NG (NVOX/4)          // 442368
#define NFEAT (BD*FD*DHW)    // 56623104
#define PLO 15872            // conf in (0.19,1.0] -> 16-bit prefix within [PLO, PLO+512)
#define NBIN 512
#define NSLOT 20             // 5 classes x 4 order statistics
#define NENT 20
#define SPIKE_PRE 16256      // 0x3F80 : bin containing only conf == 1.0
#define HGRID 592
#define SGRID (NG/512)       // 864

// ---------------- device scratch ----------------
__device__ __align__(16) unsigned g_packed[NVOX];        // label<<29 | (conf bits & 0x1FFFFFFF)
__device__ unsigned g_hist1[CD * NBIN];
__device__ __align__(16) unsigned g_histF[NENT * 65536]; // fine 16-bit histograms (5.24 MB)
__device__ __align__(16) unsigned g_chunk[NENT * 256];   // 256-chunk sums per entry
__device__ float    g_newmin[CD], g_newmax[CD];
__device__ unsigned g_done;

// ---------------- K0: zero hist1 + done (tiny; histF/chunk zeroed in k_conf) ------
__global__ void k_zero() {
    int i = blockIdx.x * blockDim.x + threadIdx.x;
    int stride = gridDim.x * blockDim.x;
    for (int j = i; j < CD * NBIN; j += stride) g_hist1[j] = 0;
    if (i == 0) g_done = 0;
}

// ---------------- K1: confidence + packed store + level-1 hist + zero histF -------
__device__ __forceinline__ float conf5(float a, float b, float c, float d, float e) {
    float y0 = a * 10.0f, y1 = b * 10.0f, y2 = c * 10.0f, y3 = d * 10.0f, y4 = e * 10.0f;
    float m = fmaxf(fmaxf(fmaxf(y0, y1), fmaxf(y2, y3)), y4);
    float s = __expf(y0 - m) + __expf(y1 - m) + __expf(y2 - m) + __expf(y3 - m) + __expf(y4 - m);
    return __fdividef(1.0f, s);
}

__global__ void k_conf(const float4* __restrict__ lg, const int4* __restrict__ lb) {
    __shared__ unsigned sh[CD * NBIN];
    for (int j = threadIdx.x; j < CD * NBIN; j += blockDim.x) sh[j] = 0;
    __syncthreads();
    int stride = gridDim.x * blockDim.x;
    int tid = blockIdx.x * blockDim.x + threadIdx.x;
    // zero fine histograms + chunk sums for the following k_fine (this kernel
    // strictly precedes it; kernel boundary orders the writes)
    {
        uint4 z = make_uint4(0, 0, 0, 0);
        for (int j = tid; j < (NENT * 65536) / 4; j += stride) __stcs((uint4*)g_histF + j, z);
        for (int j = tid; j < (NENT * 256) / 4; j += stride)   ((uint4*)g_chunk)[j] = z;
    }
    for (int g = tid; g < NG; g += stride) {
        int v = g * 4;
        int b = (v >= DHW) ? 1 : 0;
        int s4 = g - b * Q4;
        size_t base = (size_t)(b * CD) * Q4 + (size_t)s4;
        float4 L0 = __ldcs(&lg[base]);
        float4 L1 = __ldcs(&lg[base + Q4]);
        float4 L2 = __ldcs(&lg[base + 2 * (size_t)Q4]);
        float4 L3 = __ldcs(&lg[base + 3 * (size_t)Q4]);
        float4 L4 = __ldcs(&lg[base + 4 * (size_t)Q4]);
        float cf[4];
        cf[0] = conf5(L0.x, L1.x, L2.x, L3.x, L4.x);
        cf[1] = conf5(L0.y, L1.y, L2.y, L3.y, L4.y);
        cf[2] = conf5(L0.z, L1.z, L2.z, L3.z, L4.z);
        cf[3] = conf5(L0.w, L1.w, L2.w, L3.w, L4.w);
        int4 li = __ldcs(&lb[g]);
        int cc[4] = { li.x, li.y, li.z, li.w };
        unsigned pk[4];
#pragma unroll
        for (int k = 0; k < 4; k++) {
            unsigned bits = __float_as_uint(cf[k]);
            pk[k] = ((unsigned)cc[k] << 29) | (bits & 0x1FFFFFFFu);
            unsigned idx = (bits >> 16) - PLO;
            if (idx < NBIN) atomicAdd(&sh[cc[k] * NBIN + idx], 1u);
        }
        __stcs((uint4*)g_packed + g, make_uint4(pk[0], pk[1], pk[2], pk[3]));
    }
    __syncthreads();
    for (int j = threadIdx.x; j < CD * NBIN; j += blockDim.x) {
        unsigned u = sh[j];
        if (u) atomicAdd(&g_hist1[j], u);
    }
}

// ---------------- K2: find2 + fine-histogram pass + last-block select/finalize ----
__global__ void k_fine(const float* __restrict__ emin, const float* __restrict__ emax,
                       const unsigned char* __restrict__ einit) {
    __shared__ int      spre[NSLOT];
    __shared__ unsigned srank[NSLOT];
    __shared__ int      sek[NENT];
    __shared__ int      skey1[CD];      // fast path: single key per class (-1 = none)
    __shared__ int      s_m;
    __shared__ unsigned swsum[8], swpre[8];
    __shared__ unsigned s_n;
    __shared__ unsigned s_ncls[CD];
    __shared__ double   s_f05[CD], s_f95[CD];
    __shared__ unsigned sx[NSLOT];
    __shared__ bool     is_last;

    int t = threadIdx.x, lane = t & 31, warp = t >> 5;
    if (t < NSLOT) { spre[t] = -1; srank[t] = 0; }
    __syncthreads();

    // ---- find2: scan 512-bin prefix histogram per class (2 bins/thread) ----
    for (int c = 0; c < CD; c++) {
        unsigned a = g_hist1[c * NBIN + 2 * t];
        unsigned b = g_hist1[c * NBIN + 2 * t + 1];
        unsigned s = a + b;
        unsigned incl = s;
        for (int off = 1; off < 32; off <<= 1) {
            unsigned u = __shfl_up_sync(0xffffffffu, incl, off);
            if (lane >= off) incl += u;
        }
        if (lane == 31) swsum[warp] = incl;
        __syncthreads();
        if (t == 0) {
            unsigned run = 0;
#pragma unroll
            for (int w = 0; w < 8; w++) { swpre[w] = run; run += swsum[w]; }
            s_n = run;
        }
        __syncthreads();
        unsigned total = s_n;
        long long exclp = (long long)(incl - s + swpre[warp]);
        long long n = (long long)total;
        if (n == 0) {
            if (t == 0) { s_ncls[c] = 0; s_f05[c] = 0.0; s_f95[c] = 0.0; }
        } else {
            double p05 = 0.05 * (double)(n - 1);
            long long i05 = (long long)p05;
            double p95 = 0.95 * (double)(n - 1);
            long long i95 = (long long)p95;
            if (t == 0) {
                s_ncls[c] = total;
                s_f05[c] = p05 - (double)i05;
                s_f95[c] = p95 - (double)i95;
            }
            long long rr[4];
            rr[0] = i05; rr[1] = (i05 + 1 < n) ? i05 + 1 : i05;
            rr[2] = i95; rr[3] = (i95 + 1 < n) ? i95 + 1 : i95;
#pragma unroll
            for (int j = 0; j < 4; j++) {
                long long r = rr[j];
                if (r >= exclp && r < exclp + (long long)s) {
                    unsigned rem = (unsigned)(r - exclp);
                    if (rem < a) { spre[c * 4 + j] = PLO + 2 * t;     srank[c * 4 + j] = rem; }
                    else         { spre[c * 4 + j] = PLO + 2 * t + 1; srank[c * 4 + j] = rem - a; }
                }
            }
        }
        __syncthreads();
    }
    // compact entry list: dedup non-spike prefixes per class
    if (t == 0) {
        int mmax = 0;
        for (int c = 0; c < CD; c++) {
            int m = 0;
            for (int j = 0; j < 4; j++) {
                int pre = spre[c * 4 + j];
                if (pre < 0 || pre == SPIKE_PRE) continue;
                bool dup = false;
                for (int j2 = 0; j2 < j; j2++) if (spre[c * 4 + j2] == pre) { dup = true; break; }
                if (!dup) { sek[c * 4 + m] = pre & 0x1FFF; m++; }
            }
            for (int e = m; e < 4; e++) sek[c * 4 + e] = -1;
            skey1[c] = sek[c * 4 + 0];
            if (m > mmax) mmax = m;
        }
        s_m = mmax;
    }
    __syncthreads();

    // ---- fine pass over packed stream ----
    int mm = s_m;
    int stride = gridDim.x * blockDim.x;
    if (mm == 1) {
        // fast path: at most one refinement key per class
        for (int g = blockIdx.x * blockDim.x + t; g < NG; g += stride) {
            uint4 p4 = ((const uint4*)g_packed)[g];
            unsigned pks[4] = { p4.x, p4.y, p4.z, p4.w };
#pragma unroll
            for (int k = 0; k < 4; k++) {
                unsigned pk = pks[k];
                int c = (int)(pk >> 29);
                int key = (int)((pk >> 16) & 0x1FFFu);
                if (key == skey1[c]) {
                    unsigned low = pk & 0xFFFFu;
                    atomicAdd(&g_histF[(c * 4) * 65536 + low], 1u);
                    atomicAdd(&g_chunk[(c * 4) * 256 + (low >> 8)], 1u);
                }
            }
        }
    } else if (mm > 1) {
        for (int g = blockIdx.x * blockDim.x + t; g < NG; g += stride) {
            uint4 p4 = ((const uint4*)g_packed)[g];
            unsigned pks[4] = { p4.x, p4.y, p4.z, p4.w };
#pragma unroll
            for (int k = 0; k < 4; k++) {
                unsigned pk = pks[k];
                int c = (int)(pk >> 29);
                int key = (int)((pk >> 16) & 0x1FFFu);
                for (int s = 0; s < mm; s++)
                    if (sek[c * 4 + s] == key) {
                        unsigned low = pk & 0xFFFFu;
                        atomicAdd(&g_histF[(c * 4 + s) * 65536 + low], 1u);
                        atomicAdd(&g_chunk[(c * 4 + s) * 256 + (low >> 8)], 1u);
                    }
            }
        }
    }

    // ---- last-block: select order statistics via chunk sums, then EMA finalize ----
    __threadfence();
    if (t == 0) is_last = (atomicAdd(&g_done, 1u) == (unsigned)(gridDim.x - 1));
    __syncthreads();
    if (!is_last) return;

    for (int slot = warp; slot < NSLOT; slot += 8) {
        int pre = spre[slot];
        if (pre < 0 || pre == SPIKE_PRE) {
            if (lane == 0) sx[slot] = 0x3F800000u;   // spike or empty class
            continue;
        }
        int c = slot >> 2;
        int key = pre & 0x1FFF;
        int e = c * 4;
        for (int s = 0; s < 4; s++) if (sek[c * 4 + s] == key) { e = c * 4 + s; break; }
        const unsigned* hc = &g_chunk[e * 256];
        const unsigned* hf = &g_histF[e * 65536];
        unsigned rank = srank[slot];

        // scan 256 chunk sums (8 per lane)
        unsigned h[8]; unsigned sum = 0;
#pragma unroll
        for (int j = 0; j < 8; j++) { h[j] = hc[lane * 8 + j]; sum += h[j]; }
        unsigned v = sum;
        for (int off = 1; off < 32; off <<= 1) {
            unsigned u = __shfl_up_sync(0xffffffffu, v, off);
            if (lane >= off) v += u;
        }
        unsigned excl = v - sum;
        bool hit = (excl <= rank && rank < excl + sum);
        unsigned mball = __ballot_sync(0xffffffffu, hit);
        int srcl = __ffs(mball) - 1;
        int jc = 0; unsigned rem = 0;
        if (hit) {
            unsigned run = excl;
#pragma unroll
            for (int j = 0; j < 8; j++) {
                if (rank < run + h[j]) { jc = lane * 8 + j; rem = rank - run; break; }
                run += h[j];
            }
        }
        jc  = __shfl_sync(0xffffffffu, jc, srcl);
        rem = __shfl_sync(0xffffffffu, rem, srcl);

        // drill into chunk jc (256 fine bins, 8 per lane)
        unsigned f[8]; unsigned fsum = 0;
#pragma unroll
        for (int j = 0; j < 8; j++) { f[j] = hf[jc * 256 + lane * 8 + j]; fsum += f[j]; }
        unsigned fv = fsum;
        for (int off = 1; off < 32; off <<= 1) {
            unsigned u = __shfl_up_sync(0xffffffffu, fv, off);
            if (lane >= off) fv += u;
        }
        unsigned fexcl = fv - fsum;
        if (fexcl <= rem && rem < fexcl + fsum) {
            unsigned run = fexcl;
#pragma unroll
            for (int j = 0; j < 8; j++) {
                if (rem < run + f[j]) {
                    sx[slot] = ((unsigned)pre << 16) | (unsigned)(jc * 256 + lane * 8 + j);
                    break;
                }
                run += f[j];
            }
        }
    }
    __syncthreads();
    if (t < CD) {
        int c = t;
        float nmin, nmax;
        if (s_ncls[c] == 0) {
            nmin = emin[c]; nmax = emax[c];
        } else {
            float x0 = __uint_as_float(sx[c * 4 + 0]);
            float x1 = __uint_as_float(sx[c * 4 + 1]);
            float x2 = __uint_as_float(sx[c * 4 + 2]);
            float x3 = __uint_as_float(sx[c * 4 + 3]);
            float bmin = (float)((double)x0 + s_f05[c] * ((double)x1 - (double)x0));
            float bmax = (float)((double)x2 + s_f95[c] * ((double)x3 - (double)x2));
            bool ini = einit[c] != 0;
            nmin = ini ? (0.99f * emin[c] + 0.01f * bmin) : bmin;
            nmax = ini ? (0.99f * emax[c] + 0.01f * bmax) : bmax;
        }
        g_newmin[c] = nmin; g_newmax[c] = nmax;
    }
}

// ---------------- K3: gamma map + feature scaling (HBM-bound) ----------------
// Each block handles 512 consecutive voxel-groups as two 256-wide coalesced tiles.
// Q4 = 432*512, so the batch index is uniform within a block.
__global__ void k_scale(const float4* __restrict__ ft, const float* __restrict__ ranks,
                        float* __restrict__ out) {
    __shared__ float smin[CD], sinv[CD], sadd[CD], smax[CD], sint[CD];
    if (threadIdx.x < CD) {
        int c = threadIdx.x;
        float mn = g_newmin[c], mx = g_newmax[c];
        smin[c] = mn; smax[c] = mx;
        sint[c] = 1.0f - ranks[c] / 4.0f;
        if (mx > mn) { sinv[c] = 1.0f / (mx - mn + 1e-8f); sadd[c] = 0.0f; }
        else         { sinv[c] = 0.0f;                     sadd[c] = 0.5f; }
    }
    __syncthreads();
    int g0 = blockIdx.x * 512 + threadIdx.x;   // tile 0
    int g1 = g0 + 256;                          // tile 1
    uint4 pa = ((const uint4*)g_packed)[g0];
    uint4 pb = ((const uint4*)g_packed)[g1];
    unsigned pks[8] = { pa.x, pa.y, pa.z, pa.w, pb.x, pb.y, pb.z, pb.w };

    float gm[8];
#pragma unroll
    for (int k = 0; k < 8; k++) {
        unsigned pk = pks[k];
        int c = (int)(pk >> 29);
        float cv = __uint_as_float((pk & 0x1FFFFFFFu) | 0x20000000u);
        float mn = smin[c], mx = smax[c];
        float cl = fminf(fmaxf(cv, mn), mx);
        float nr = (cl - mn) * sinv[c] + sadd[c];
        gm[k] = 1.0f + sint[c] * (1.0f + 0.5f * (1.0f - nr));
    }
    __stcs((float4*)(out + NFEAT) + g0, make_float4(gm[0], gm[1], gm[2], gm[3]));
    __stcs((float4*)(out + NFEAT) + g1, make_float4(gm[4], gm[5], gm[6], gm[7]));

    int b = (g0 >= Q4) ? 1 : 0;                 // uniform per block
    size_t fbase = (size_t)(b * FD) * Q4 + (size_t)(g0 - b * Q4);
    float4* o4 = (float4*)out;
#pragma unroll 4
    for (int f = 0; f < FD; f++) {
        size_t off = fbase + (size_t)f * Q4;
        float4 x0 = __ldcs(&ft[off]);
        float4 x1 = __ldcs(&ft[off + 256]);
        x0.x *= gm[0]; x0.y *= gm[1]; x0.z *= gm[2]; x0.w *= gm[3];
        x1.x *= gm[4]; x1.y *= gm[5]; x1.z *= gm[6]; x1.w *= gm[7];
        __stcs(&o4[off], x0);
        __stcs(&o4[off + 256], x1);
    }
}

// ---------------- launch ----------------
extern "C" void kernel_launch(void* const* d_in, const int* in_sizes, int n_in,
                              void* d_out, int out_size) {
    const float* feat          = (const float*)d_in[0];
    const float* logits        = (const float*)d_in[1];
    const int*   labels        = (const int*)d_in[2];
    const float* ranks         = (const float*)d_in[3];
    const float* emin          = (const float*)d_in[4];
    const float* emax          = (const float*)d_in[5];
    const unsigned char* einit = (const unsigned char*)d_in[6];
    float* out = (float*)d_out;
    (void)in_sizes; (void)n_in; (void)out_size;

    k_zero<<<8, 256>>>();
    k_conf<<<HGRID, 256>>>((const float4*)logits, (const int4*)labels);
    k_fine<<<HGRID, 256>>>(emin, emax, einit);
    k_scale<<<SGRID, 256>>>((const float4*)feat, ranks, out);
}